// round 1
// baseline (speedup 1.0000x reference)
#include <cuda_runtime.h>
#include <math.h>

// Problem constants
#define BB 2
#define HH 8
#define SS 2048
#define DD 128
#define HD 1024          // H*D
#define THD 2048         // 2*H*D
#define SD 262144        // S*D
#define SHD 2097152      // S*H*D
#define NROWS 32768      // B*H*S
#define ATTN_ELEMS 67108864ULL   // B*H*S*S
#define OUT_ELEMS 524288         // B*S*D
#define SCALE 0.088388347648318440550f  // 1/sqrt(128)

// ---------------- scratch (device globals; no allocation allowed) ----------------
__device__ float g_q[BB * SS * THD];     // (B,S,2HD) projection buffer, 32MB
__device__ float g_k[BB * SS * THD];     // 32MB
__device__ float g_v[BB * SS * HD];      // 16MB
__device__ float g_s2[ATTN_ELEMS];       // raw s2 scores, 256MB
__device__ float g_obuf[BB * SS * HD];   // attention output in [b][s][h][d] layout, 16MB
__device__ float g_max1[NROWS], g_sum1[NROWS];
__device__ float g_max2[NROWS], g_sum2[NROWS];
__device__ float g_psum[512], g_psumsq[512];
__device__ float g_acoef[16], g_ccoef[16];   // per (b,h) affine for fused groupnorm

// ---------------- QKV projection: C[n,m] = sum_d A[n,d]*W[m,d] + bias[m] ----------------
// A: (4096 x 128), W: (N x 128). BM=BN=64, BK=32, 256 threads, 4x4 microtile.
__global__ void proj_kernel(const float* __restrict__ A, const float* __restrict__ W,
                            const float* __restrict__ bias, float* __restrict__ C, int N)
{
    __shared__ float As[64][33];
    __shared__ float Ws[64][33];
    const int m0 = blockIdx.x * 64;
    const int n0 = blockIdx.y * 64;
    const int tid = threadIdx.x;
    const int tx = tid & 15, ty = tid >> 4;
    float acc[4][4] = {};
    for (int k0 = 0; k0 < 128; k0 += 32) {
        #pragma unroll
        for (int i = tid; i < 64 * 32; i += 256) {
            int r = i >> 5, c = i & 31;
            As[r][c] = A[(size_t)(m0 + r) * 128 + k0 + c];
            Ws[r][c] = W[(size_t)(n0 + r) * 128 + k0 + c];
        }
        __syncthreads();
        #pragma unroll
        for (int kk = 0; kk < 32; kk++) {
            float a[4], w[4];
            #pragma unroll
            for (int i = 0; i < 4; i++) a[i] = As[ty * 4 + i][kk];
            #pragma unroll
            for (int j = 0; j < 4; j++) w[j] = Ws[tx * 4 + j][kk];
            #pragma unroll
            for (int i = 0; i < 4; i++)
                #pragma unroll
                for (int j = 0; j < 4; j++) acc[i][j] = fmaf(a[i], w[j], acc[i][j]);
        }
        __syncthreads();
    }
    #pragma unroll
    for (int i = 0; i < 4; i++) {
        int m = m0 + ty * 4 + i;
        #pragma unroll
        for (int j = 0; j < 4; j++) {
            int n = n0 + tx * 4 + j;
            C[(size_t)m * N + n] = acc[i][j] + bias[n];
        }
    }
}

// ---------------- scores: per (b,h), S_part = scale * Qp * Kp^T  ----------------
// Q/K rows have stride 256 floats; part selects cols [0,128) or [128,256).
// toS2==0: write to attn region (passed ptr). toS2==1: write to g_s2.
__global__ void scores_kernel(float* __restrict__ Cout, int colOff, int toS2)
{
    const int z = blockIdx.z;                      // b*H + h
    const float* Aq = g_q + (size_t)z * 524288 + colOff;
    const float* Ak = g_k + (size_t)z * 524288 + colOff;
    float* C = (toS2 ? g_s2 : Cout) + (size_t)z * SS * SS;

    __shared__ float As[64][33];
    __shared__ float Bs[64][33];
    const int q0 = blockIdx.x * 64;
    const int n0 = blockIdx.y * 64;
    const int tid = threadIdx.x;
    const int tx = tid & 15, ty = tid >> 4;
    float acc[4][4] = {};
    for (int k0 = 0; k0 < 128; k0 += 32) {
        #pragma unroll
        for (int i = tid; i < 64 * 32; i += 256) {
            int r = i >> 5, c = i & 31;
            As[r][c] = Aq[(size_t)(q0 + r) * 256 + k0 + c];
            Bs[r][c] = Ak[(size_t)(n0 + r) * 256 + k0 + c];
        }
        __syncthreads();
        #pragma unroll
        for (int kk = 0; kk < 32; kk++) {
            float a[4], w[4];
            #pragma unroll
            for (int i = 0; i < 4; i++) a[i] = As[ty * 4 + i][kk];
            #pragma unroll
            for (int j = 0; j < 4; j++) w[j] = Bs[tx * 4 + j][kk];
            #pragma unroll
            for (int i = 0; i < 4; i++)
                #pragma unroll
                for (int j = 0; j < 4; j++) acc[i][j] = fmaf(a[i], w[j], acc[i][j]);
        }
        __syncthreads();
    }
    #pragma unroll
    for (int i = 0; i < 4; i++) {
        int q = q0 + ty * 4 + i;
        #pragma unroll
        for (int j = 0; j < 4; j++) {
            int n = n0 + tx * 4 + j;
            C[(size_t)q * SS + n] = acc[i][j] * SCALE;
        }
    }
}

// ---------------- row softmax stats: max + sum(exp(x-max)) per 2048-row ----------------
// which==0: read from s1base (attn region), write g_max1/g_sum1.
// which==1: read from g_s2, write g_max2/g_sum2.
__global__ void row_stats_kernel(const float* __restrict__ s1base, int which)
{
    const size_t row = blockIdx.x;
    const float* p = (which ? g_s2 : s1base) + row * 2048;
    const int tid = threadIdx.x;
    const float4* p4 = (const float4*)p;
    float4 v0 = p4[tid];
    float4 v1 = p4[tid + 256];

    float m = fmaxf(fmaxf(fmaxf(v0.x, v0.y), fmaxf(v0.z, v0.w)),
                    fmaxf(fmaxf(v1.x, v1.y), fmaxf(v1.z, v1.w)));
    __shared__ float red[8];
    int lane = tid & 31, warp = tid >> 5;
    #pragma unroll
    for (int off = 16; off > 0; off >>= 1) m = fmaxf(m, __shfl_xor_sync(0xffffffffu, m, off));
    if (lane == 0) red[warp] = m;
    __syncthreads();
    if (tid < 32) {
        float t = (tid < 8) ? red[tid] : -1e30f;
        #pragma unroll
        for (int off = 4; off > 0; off >>= 1) t = fmaxf(t, __shfl_xor_sync(0xffffffffu, t, off));
        if (tid == 0) red[0] = t;
    }
    __syncthreads();
    m = red[0];
    __syncthreads();

    float s = expf(v0.x - m) + expf(v0.y - m) + expf(v0.z - m) + expf(v0.w - m)
            + expf(v1.x - m) + expf(v1.y - m) + expf(v1.z - m) + expf(v1.w - m);
    #pragma unroll
    for (int off = 16; off > 0; off >>= 1) s += __shfl_xor_sync(0xffffffffu, s, off);
    if (lane == 0) red[warp] = s;
    __syncthreads();
    if (tid < 32) {
        float t = (tid < 8) ? red[tid] : 0.f;
        #pragma unroll
        for (int off = 4; off > 0; off >>= 1) t += __shfl_xor_sync(0xffffffffu, t, off);
        if (tid == 0) {
            if (which) { g_max2[row] = m; g_sum2[row] = t; }
            else       { g_max1[row] = m; g_sum1[row] = t; }
        }
    }
}

// ---------------- combine: attn = softmax(s1) - lam*softmax(s2), in place over s1 ----------------
__global__ void combine_kernel(float* __restrict__ attn, const float* __restrict__ lamp)
{
    const size_t row = blockIdx.x;
    const float lam = lamp[0];
    const float m1 = g_max1[row], i1 = 1.0f / g_sum1[row];
    const float m2 = g_max2[row], i2 = 1.0f / g_sum2[row];
    float4* a = (float4*)(attn + row * 2048);
    const float4* b = (const float4*)(g_s2 + row * 2048);
    for (int i = threadIdx.x; i < 512; i += 256) {
        float4 x = a[i];
        float4 y = b[i];
        x.x = expf(x.x - m1) * i1 - lam * expf(y.x - m2) * i2;
        x.y = expf(x.y - m1) * i1 - lam * expf(y.y - m2) * i2;
        x.z = expf(x.z - m1) * i1 - lam * expf(y.z - m2) * i2;
        x.w = expf(x.w - m1) * i1 - lam * expf(y.w - m2) * i2;
        a[i] = x;
    }
}

// ---------------- attn @ V -> obuf in [b][s][h][d] layout ----------------
// Per (b,h): C(2048x128) = attn(2048x2048) * V(2048x128). BM=64, BN=128, BK=32.
__global__ void av_kernel(const float* __restrict__ attn)
{
    const int z = blockIdx.z;
    const int b = z >> 3, h = z & 7;
    const float* A = attn + (size_t)z * SS * SS;
    const float* Vp = g_v + (size_t)z * SD;

    __shared__ float As[64][33];
    __shared__ float Vs[32][128];
    const int q0 = blockIdx.x * 64;
    const int tid = threadIdx.x;
    const int tx = tid & 15, ty = tid >> 4;
    float acc[4][8] = {};
    for (int k0 = 0; k0 < 2048; k0 += 32) {
        #pragma unroll
        for (int i = tid; i < 64 * 32; i += 256) {
            int r = i >> 5, c = i & 31;
            As[r][c] = A[(size_t)(q0 + r) * 2048 + k0 + c];
        }
        #pragma unroll
        for (int i = tid; i < 32 * 128; i += 256) {
            int r = i >> 7, c = i & 127;
            Vs[r][c] = Vp[(size_t)(k0 + r) * 128 + c];
        }
        __syncthreads();
        #pragma unroll
        for (int kk = 0; kk < 32; kk++) {
            float a[4], v[8];
            #pragma unroll
            for (int i = 0; i < 4; i++) a[i] = As[ty * 4 + i][kk];
            #pragma unroll
            for (int j = 0; j < 8; j++) v[j] = Vs[kk][tx * 8 + j];
            #pragma unroll
            for (int i = 0; i < 4; i++)
                #pragma unroll
                for (int j = 0; j < 8; j++) acc[i][j] = fmaf(a[i], v[j], acc[i][j]);
        }
        __syncthreads();
    }
    #pragma unroll
    for (int i = 0; i < 4; i++) {
        int q = q0 + ty * 4 + i;
        float* dst = g_obuf + (size_t)b * SHD + (size_t)q * HD + h * DD;
        #pragma unroll
        for (int j = 0; j < 8; j++) dst[tx * 8 + j] = acc[i][j];
    }
}

// ---------------- group norm stage 1: partial sums over 8192-float chunks ----------------
__global__ void gn_partial_kernel()
{
    const int blk = blockIdx.x;   // 512 blocks; group = blk/32, contiguous overall
    const float4* p = (const float4*)(g_obuf + (size_t)blk * 8192);
    float s = 0.f, ss = 0.f;
    for (int i = threadIdx.x; i < 2048; i += 256) {
        float4 v = p[i];
        s += v.x + v.y + v.z + v.w;
        ss += v.x * v.x + v.y * v.y + v.z * v.z + v.w * v.w;
    }
    __shared__ float rs[8], rss[8];
    int lane = threadIdx.x & 31, warp = threadIdx.x >> 5;
    #pragma unroll
    for (int off = 16; off > 0; off >>= 1) {
        s += __shfl_xor_sync(0xffffffffu, s, off);
        ss += __shfl_xor_sync(0xffffffffu, ss, off);
    }
    if (lane == 0) { rs[warp] = s; rss[warp] = ss; }
    __syncthreads();
    if (threadIdx.x < 32) {
        float t = (threadIdx.x < 8) ? rs[threadIdx.x] : 0.f;
        float tt = (threadIdx.x < 8) ? rss[threadIdx.x] : 0.f;
        #pragma unroll
        for (int off = 4; off > 0; off >>= 1) {
            t += __shfl_xor_sync(0xffffffffu, t, off);
            tt += __shfl_xor_sync(0xffffffffu, tt, off);
        }
        if (threadIdx.x == 0) { g_psum[blk] = t; g_psumsq[blk] = tt; }
    }
}

// ---------------- group norm stage 2: finalize affine coefficients ----------------
__global__ void gn_final_kernel(const float* __restrict__ gnw, const float* __restrict__ gnb,
                                const float* __restrict__ li)
{
    const int g = blockIdx.x;   // 16 groups, 32 threads each
    const int t = threadIdx.x;
    float s = g_psum[g * 32 + t];
    float ss = g_psumsq[g * 32 + t];
    #pragma unroll
    for (int off = 16; off > 0; off >>= 1) {
        s += __shfl_xor_sync(0xffffffffu, s, off);
        ss += __shfl_xor_sync(0xffffffffu, ss, off);
    }
    if (t == 0) {
        const float inv_n = 1.0f / (float)SD;
        float mean = s * inv_n;
        float var = ss * inv_n - mean * mean;
        float rstd = rsqrtf(var + 1e-5f);
        int h = g & 7;
        float k = 1.0f - li[0];
        g_acoef[g] = rstd * gnw[h] * k;
        g_ccoef[g] = (gnb[h] - mean * rstd * gnw[h]) * k;
    }
}

// ---------------- output projection with fused normalize+gather ----------------
// Y(4096 x 128) = Anorm(4096 x 1024) * Wo^T + bo
// Anorm[b*S+s][m] = obuf[b][ (m>>7)*SD + s*128 + (m&127) ] * acoef + ccoef
__global__ void outproj_kernel(const float* __restrict__ Wo, const float* __restrict__ bo,
                               float* __restrict__ Y)
{
    __shared__ float As[64][33];
    __shared__ float Ws[128][33];
    const int row0 = blockIdx.x * 64;
    const int b = row0 >> 11;
    const int s0 = row0 & 2047;
    const int tid = threadIdx.x;
    const int tx = tid & 15, ty = tid >> 4;
    float acc[4][8] = {};
    for (int k0 = 0; k0 < 1024; k0 += 32) {
        const int h = k0 >> 7;
        const int e0 = k0 & 127;
        const float ac = g_acoef[b * 8 + h];
        const float cc = g_ccoef[b * 8 + h];
        const float* src = g_obuf + (size_t)b * SHD + (size_t)h * SD;
        #pragma unroll
        for (int i = tid; i < 64 * 32; i += 256) {
            int r = i >> 5, c = i & 31;
            As[r][c] = src[(size_t)(s0 + r) * 128 + e0 + c] * ac + cc;
        }
        #pragma unroll
        for (int i = tid; i < 128 * 32; i += 256) {
            int r = i >> 5, c = i & 31;
            Ws[r][c] = Wo[(size_t)r * 1024 + k0 + c];
        }
        __syncthreads();
        #pragma unroll
        for (int kk = 0; kk < 32; kk++) {
            float a[4], w[8];
            #pragma unroll
            for (int i = 0; i < 4; i++) a[i] = As[ty * 4 + i][kk];
            #pragma unroll
            for (int j = 0; j < 8; j++) w[j] = Ws[tx * 8 + j][kk];
            #pragma unroll
            for (int i = 0; i < 4; i++)
                #pragma unroll
                for (int j = 0; j < 8; j++) acc[i][j] = fmaf(a[i], w[j], acc[i][j]);
        }
        __syncthreads();
    }
    #pragma unroll
    for (int i = 0; i < 4; i++) {
        int r = row0 + ty * 4 + i;
        #pragma unroll
        for (int j = 0; j < 8; j++) {
            int n = tx * 8 + j;
            Y[(size_t)r * 128 + n] = acc[i][j] + bo[n];
        }
    }
}

// ---------------- launcher ----------------
extern "C" void kernel_launch(void* const* d_in, const int* in_sizes, int n_in,
                              void* d_out, int out_size)
{
    const float* x   = (const float*)d_in[0];
    const float* Wq  = (const float*)d_in[1];
    const float* bq  = (const float*)d_in[2];
    const float* Wk  = (const float*)d_in[3];
    const float* bk  = (const float*)d_in[4];
    const float* Wv  = (const float*)d_in[5];
    const float* bv  = (const float*)d_in[6];
    const float* Wo  = (const float*)d_in[7];
    const float* bo  = (const float*)d_in[8];
    const float* lam = (const float*)d_in[9];
    const float* li  = (const float*)d_in[10];
    const float* gnw = (const float*)d_in[11];
    const float* gnb = (const float*)d_in[12];

    float* out_y = (float*)d_out;               // (B,S,D) = 524288 floats
    float* attn  = out_y + OUT_ELEMS;           // (B,H,S,S) = 67108864 floats

    // 1) projections
    // NOTE: g_q/g_k/g_v are referenced directly inside kernels; proj writes via passed C.
    {
        float* gq; cudaGetSymbolAddress((void**)&gq, g_q);
        float* gk; cudaGetSymbolAddress((void**)&gk, g_k);
        float* gv; cudaGetSymbolAddress((void**)&gv, g_v);
        proj_kernel<<<dim3(64, 32), 256>>>(x, Wq, bq, gq, 2048);
        proj_kernel<<<dim3(64, 32), 256>>>(x, Wk, bk, gk, 2048);
        proj_kernel<<<dim3(64, 16), 256>>>(x, Wv, bv, gv, 1024);
    }

    // 2) raw scores: s1 -> attn region, s2 -> g_s2
    scores_kernel<<<dim3(32, 32, 16), 256>>>(attn, 0, 0);
    scores_kernel<<<dim3(32, 32, 16), 256>>>(attn, 128, 1);

    // 3) softmax row stats
    row_stats_kernel<<<NROWS, 256>>>(attn, 0);
    row_stats_kernel<<<NROWS, 256>>>(attn, 1);

    // 4) differential combine (in-place into attn output region)
    combine_kernel<<<NROWS, 256>>>(attn, lam);

    // 5) attn @ V
    av_kernel<<<dim3(32, 1, 16), 256>>>(attn);

    // 6) group norm
    gn_partial_kernel<<<512, 256>>>();
    gn_final_kernel<<<16, 32>>>(gnw, gnb, li);

    // 7) fused normalize + output projection
    outproj_kernel<<<64, 256>>>(Wo, bo, out_y);
}